// round 1
// baseline (speedup 1.0000x reference)
#include <cuda_runtime.h>
#include <cuda_bf16.h>

#define HD    64      // hidden dim
#define G4    256     // 4*HD gates
#define PB    64      // peds per LSTM block
#define TPB   256
#define DCOL  544     // dist_fc_input width = 256 + 256 + 32
#define MLPW  32
#define ZS    32

__device__ __forceinline__ float sigf(float x) { return 1.0f / (1.0f + __expf(-x)); }
__device__ __forceinline__ float tanhfast(float x) { return 2.0f / (1.0f + __expf(-2.0f * x)) - 1.0f; }

// ---------------------------------------------------------------------------
// K1: bidirectional LSTM. grid = (B/PB, 2); blockIdx.y = 0 fwd, 1 rev.
// Writes h -> out cols [rev*64, rev*64+64), c -> out cols [128+rev*64, ...).
// smem: w_hh (64x256) | w_ih (2x256) | bias (256) | h_s (64x64, k-major)
// ---------------------------------------------------------------------------
__global__ void lstm_kernel(
    const float* __restrict__ last_obs, const float* __restrict__ xseq,
    const float* __restrict__ w_h0, const float* __restrict__ b_h0,
    const float* __restrict__ w_c0, const float* __restrict__ b_c0,
    const float* __restrict__ w_ih_f, const float* __restrict__ w_hh_f, const float* __restrict__ b_f,
    const float* __restrict__ w_ih_r, const float* __restrict__ w_hh_r, const float* __restrict__ b_r,
    float* __restrict__ out, int B, int T)
{
    extern __shared__ float sm[];
    float* w_s   = sm;                    // 16384 floats
    float* wih_s = w_s + HD * G4;         // 512
    float* b_s   = wih_s + 2 * G4;        // 256
    float* h_s   = b_s + G4;              // 4096  (layout [k][p])

    const int rev = blockIdx.y;
    const float* w_hh = rev ? w_hh_r : w_hh_f;
    const float* w_ih = rev ? w_ih_r : w_ih_f;
    const float* bias = rev ? b_r    : b_f;

    const int tid = threadIdx.x;
    const int pb  = blockIdx.x * PB;

    for (int i = tid; i < (HD * G4) / 4; i += TPB)
        ((float4*)w_s)[i] = ((const float4*)w_hh)[i];
    for (int i = tid; i < (2 * G4) / 4; i += TPB)
        ((float4*)wih_s)[i] = ((const float4*)w_ih)[i];
    for (int i = tid; i < G4 / 4; i += TPB)
        ((float4*)b_s)[i] = ((const float4*)bias)[i];

    const int tp = tid & 15;   // ped group -> peds [tp*4, tp*4+4)
    const int td = tid >> 4;   // d group   -> dims [td*4, td*4+4)
    const int p0 = tp * 4;
    const int d0 = td * 4;

    float creg[4][4];   // [p][dd], persistent cell state

    if (!rev) {
        // h0 = last_obs @ w_h0 + b_h0 ; c0 = last_obs @ w_c0 + b_c0
        #pragma unroll
        for (int p = 0; p < 4; p++) {
            const float* lo = last_obs + (size_t)(pb + p0 + p) * 6;
            float l[6];
            #pragma unroll
            for (int k = 0; k < 6; k++) l[k] = lo[k];
            #pragma unroll
            for (int dd = 0; dd < 4; dd++) {
                const int d = d0 + dd;
                float ha = b_h0[d], ca = b_c0[d];
                #pragma unroll
                for (int k = 0; k < 6; k++) {
                    ha += l[k] * w_h0[k * HD + d];
                    ca += l[k] * w_c0[k * HD + d];
                }
                h_s[d * PB + p0 + p] = ha;
                creg[p][dd] = ca;
            }
        }
    } else {
        #pragma unroll
        for (int p = 0; p < 4; p++)
            #pragma unroll
            for (int dd = 0; dd < 4; dd++) {
                h_s[(d0 + dd) * PB + p0 + p] = 0.f;
                creg[p][dd] = 0.f;
            }
    }
    __syncthreads();

    for (int s = 0; s < T; s++) {
        const int t = rev ? (T - 1 - s) : s;

        float x0[4], x1[4];
        #pragma unroll
        for (int p = 0; p < 4; p++) {
            const float2 xv = ((const float2*)xseq)[(size_t)t * B + pb + p0 + p];
            x0[p] = xv.x; x1[p] = xv.y;
        }

        float acc[4][4][4];   // [p][gate][dd]
        #pragma unroll
        for (int g = 0; g < 4; g++)
            #pragma unroll
            for (int dd = 0; dd < 4; dd++) {
                const int j = g * HD + d0 + dd;
                const float bj = b_s[j], wi0 = wih_s[j], wi1 = wih_s[G4 + j];
                #pragma unroll
                for (int p = 0; p < 4; p++)
                    acc[p][g][dd] = bj + x0[p] * wi0 + x1[p] * wi1;
            }

        #pragma unroll 4
        for (int k = 0; k < HD; k++) {
            const float4 hv = *(const float4*)&h_s[k * PB + p0];
            const float hp[4] = {hv.x, hv.y, hv.z, hv.w};
            #pragma unroll
            for (int g = 0; g < 4; g++) {
                const float4 wv = *(const float4*)&w_s[k * G4 + g * HD + d0];
                const float wr[4] = {wv.x, wv.y, wv.z, wv.w};
                #pragma unroll
                for (int p = 0; p < 4; p++)
                    #pragma unroll
                    for (int dd = 0; dd < 4; dd++)
                        acc[p][g][dd] += hp[p] * wr[dd];
            }
        }
        __syncthreads();   // all reads of h_s done

        #pragma unroll
        for (int dd = 0; dd < 4; dd++) {
            float hnew[4];
            #pragma unroll
            for (int p = 0; p < 4; p++) {
                const float zi = acc[p][0][dd], zf = acc[p][1][dd];
                const float zg = acc[p][2][dd], zo = acc[p][3][dd];
                const float c = sigf(zf) * creg[p][dd] + sigf(zi) * tanhfast(zg);
                creg[p][dd] = c;
                hnew[p] = sigf(zo) * tanhfast(c);
            }
            *(float4*)&h_s[(d0 + dd) * PB + p0] =
                make_float4(hnew[0], hnew[1], hnew[2], hnew[3]);
        }
        __syncthreads();   // h_s updated for next step
    }

    // write final h (from h_s) and c (from regs) into out cols
    const int cb = rev * HD;
    #pragma unroll
    for (int p = 0; p < 4; p++) {
        float* orow = out + (size_t)(pb + p0 + p) * DCOL;
        #pragma unroll
        for (int dd = 0; dd < 4; dd++) {
            orow[cb + d0 + dd]       = h_s[(d0 + dd) * PB + p0 + p];
            orow[128 + cb + d0 + dd] = creg[p][dd];
        }
    }
}

// ---------------------------------------------------------------------------
// K2: per-scene attention pooling. grid = S blocks, 256 threads.
// Reads out cols [0,256); writes pool -> cols [256,512); copies obs -> [512,544).
// ---------------------------------------------------------------------------
#define ESTR 260   // padded row stride for E tile (bank-conflict avoidance)
#define ASTR 68

__global__ void attn_kernel(float* __restrict__ out, const float* __restrict__ obs)
{
    extern __shared__ float sm[];
    float* E = sm;               // 64 x ESTR
    float* A = E + 64 * ESTR;    // 64 x ASTR

    const int tid = threadIdx.x;
    const int pbase = blockIdx.x * 64;

    // load E tile: 64 rows x 256 cols (as 64 float4 per row)
    for (int i = tid; i < 64 * 64; i += TPB) {
        const int p = i >> 6, c4 = i & 63;
        ((float4*)&E[p * ESTR])[c4] =
            ((const float4*)(out + (size_t)(pbase + p) * DCOL))[c4];
    }
    __syncthreads();

    // gram: G[p][q] = E[p] . E[q], thread tile 4x4
    {
        const int tq = tid & 15, tpp = tid >> 4;
        const int q0 = tq * 4, pg0 = tpp * 4;
        float acc[4][4] = {};
        for (int d4 = 0; d4 < 64; d4++) {
            float4 av[4], bv[4];
            #pragma unroll
            for (int i = 0; i < 4; i++) av[i] = *(const float4*)&E[(pg0 + i) * ESTR + d4 * 4];
            #pragma unroll
            for (int i = 0; i < 4; i++) bv[i] = *(const float4*)&E[(q0 + i) * ESTR + d4 * 4];
            #pragma unroll
            for (int i = 0; i < 4; i++)
                #pragma unroll
                for (int j = 0; j < 4; j++)
                    acc[i][j] += av[i].x * bv[j].x + av[i].y * bv[j].y
                               + av[i].z * bv[j].z + av[i].w * bv[j].w;
        }
        #pragma unroll
        for (int i = 0; i < 4; i++)
            #pragma unroll
            for (int j = 0; j < 4; j++)
                A[(pg0 + i) * ASTR + q0 + j] = acc[i][j];
    }
    __syncthreads();

    // row softmax (64 rows, one thread each)
    if (tid < 64) {
        float m = -1e30f;
        for (int q = 0; q < 64; q++) m = fmaxf(m, A[tid * ASTR + q]);
        float ssum = 0.f;
        for (int q = 0; q < 64; q++) {
            const float e = __expf(A[tid * ASTR + q] - m);
            A[tid * ASTR + q] = e;
            ssum += e;
        }
        const float inv = 1.0f / ssum;
        for (int q = 0; q < 64; q++) A[tid * ASTR + q] *= inv;
    }
    __syncthreads();

    // pool[p][d] = sum_q A[p][q] * E[q][d], thread tile 4p x 16d
    {
        const int tp2 = tid & 15, td2 = tid >> 4;
        const int pp0 = tp2 * 4, dd0 = td2 * 16;
        float pacc[4][16] = {};
        for (int q = 0; q < 64; q++) {
            float a4[4];
            #pragma unroll
            for (int i = 0; i < 4; i++) a4[i] = A[(pp0 + i) * ASTR + q];
            #pragma unroll
            for (int c4 = 0; c4 < 4; c4++) {
                const float4 ev = *(const float4*)&E[q * ESTR + dd0 + c4 * 4];
                #pragma unroll
                for (int i = 0; i < 4; i++) {
                    pacc[i][c4 * 4 + 0] += a4[i] * ev.x;
                    pacc[i][c4 * 4 + 1] += a4[i] * ev.y;
                    pacc[i][c4 * 4 + 2] += a4[i] * ev.z;
                    pacc[i][c4 * 4 + 3] += a4[i] * ev.w;
                }
            }
        }
        #pragma unroll
        for (int i = 0; i < 4; i++) {
            float* orow = out + (size_t)(pbase + pp0 + i) * DCOL + 256 + dd0;
            #pragma unroll
            for (int c4 = 0; c4 < 4; c4++)
                *(float4*)&orow[c4 * 4] = make_float4(
                    pacc[i][c4 * 4 + 0], pacc[i][c4 * 4 + 1],
                    pacc[i][c4 * 4 + 2], pacc[i][c4 * 4 + 3]);
        }
    }

    // copy obs_enc_feat into cols [512, 544)
    for (int i = tid; i < 64 * MLPW; i += TPB) {
        const int p = i >> 5, c = i & 31;
        out[(size_t)(pbase + p) * DCOL + 512 + c] = obs[(size_t)(pbase + p) * MLPW + c];
    }
}

// ---------------------------------------------------------------------------
// K3: stats = dist_fc_input @ w_fc2 + b_fc2. grid = B/256 blocks, 256 threads.
// Each block handles 256 rows (8 passes of 32 rows); thread computes 4 out cols.
// ---------------------------------------------------------------------------
__global__ void fc2_kernel(const float* __restrict__ dfi, const float* __restrict__ w,
                           const float* __restrict__ bz, float* __restrict__ stats)
{
    extern __shared__ float ws[];   // 544*32
    const int tid = threadIdx.x;
    for (int i = tid; i < (DCOL * ZS) / 4; i += TPB)
        ((float4*)ws)[i] = ((const float4*)w)[i];
    __syncthreads();

    const int og = tid & 7, rl = tid >> 3;
    const int o0 = og * 4;
    const int rowbase = blockIdx.x * 256;

    for (int pass = 0; pass < 8; pass++) {
        const int row = rowbase + pass * 32 + rl;
        const float* dr = dfi + (size_t)row * DCOL;
        float a0 = bz[o0], a1 = bz[o0 + 1], a2 = bz[o0 + 2], a3 = bz[o0 + 3];
        #pragma unroll 4
        for (int j = 0; j < DCOL; j++) {
            const float d = __ldg(dr + j);
            const float4 wv = *(const float4*)&ws[j * ZS + o0];
            a0 += d * wv.x; a1 += d * wv.y; a2 += d * wv.z; a3 += d * wv.w;
        }
        float* so = stats + (size_t)row * ZS + o0;
        so[0] = a0; so[1] = a1; so[2] = a2; so[3] = a3;
    }
}

// ---------------------------------------------------------------------------
extern "C" void kernel_launch(void* const* d_in, const int* in_sizes, int n_in,
                              void* d_out, int out_size)
{
    const float* last_obs = (const float*)d_in[0];
    const float* xseq     = (const float*)d_in[1];
    // d_in[2] = seq_start_end (uniform segments, unused)
    const float* obs      = (const float*)d_in[3];
    // d_in[4] = fut_obst (unused by forward)
    const float* w_h0     = (const float*)d_in[5];
    const float* b_h0     = (const float*)d_in[6];
    const float* w_c0     = (const float*)d_in[7];
    const float* b_c0     = (const float*)d_in[8];
    const float* w_ih_f   = (const float*)d_in[9];
    const float* w_hh_f   = (const float*)d_in[10];
    const float* b_f      = (const float*)d_in[11];
    const float* w_ih_r   = (const float*)d_in[12];
    const float* w_hh_r   = (const float*)d_in[13];
    const float* b_r      = (const float*)d_in[14];
    const float* w_fc2    = (const float*)d_in[15];
    const float* b_fc2    = (const float*)d_in[16];
    float* out = (float*)d_out;

    const int B = in_sizes[0] / 6;
    const int T = in_sizes[1] / (B * 2);
    const int S = in_sizes[2] / 2;

    const int smem_lstm = (HD * G4 + 2 * G4 + G4 + HD * PB) * 4;      // 84992
    const int smem_attn = (64 * ESTR + 64 * ASTR) * 4;                // 83968
    const int smem_fc2  = DCOL * ZS * 4;                              // 69632

    cudaFuncSetAttribute(lstm_kernel, cudaFuncAttributeMaxDynamicSharedMemorySize, smem_lstm);
    cudaFuncSetAttribute(attn_kernel, cudaFuncAttributeMaxDynamicSharedMemorySize, smem_attn);
    cudaFuncSetAttribute(fc2_kernel,  cudaFuncAttributeMaxDynamicSharedMemorySize, smem_fc2);

    dim3 g1(B / PB, 2);
    lstm_kernel<<<g1, TPB, smem_lstm>>>(last_obs, xseq,
                                        w_h0, b_h0, w_c0, b_c0,
                                        w_ih_f, w_hh_f, b_f,
                                        w_ih_r, w_hh_r, b_r,
                                        out, B, T);

    attn_kernel<<<S, TPB, smem_attn>>>(out, obs);

    float* stats = out + (size_t)B * DCOL;
    fc2_kernel<<<B / 256, TPB, smem_fc2>>>(out, w_fc2, b_fc2, stats);
}